// round 8
// baseline (speedup 1.0000x reference)
#include <cuda_runtime.h>
#include <cuda_bf16.h>
#include <math.h>
#include <stdint.h>

// ---------------- problem constants ----------------
#define S_   2048
#define HID_ 2048
#define H_   16
#define NOPE_ 128
#define ROPE_ 64
#define VD_  128
#define QH_  192
#define QL_  1536
#define KVL_ 512
#define CKV_ 576
#define INTER_ 8192
#define HQH_ 3072
#define KVOUT_ 256
#define KFD_ 192

// ---------------- scratch ----------------
#define OFF_H1       0L
#define OFF_QA       4194304L
#define OFF_Q        7340032L
#define OFF_CKV      13631488L
#define OFF_KVLN     14811136L
#define OFF_KV       15859712L
#define OFF_KF       16384000L
#define OFF_KFT      16777216L
#define OFF_ATTNO    17170432L
#define OFF_ATTNPROJ 21364736L
#define OFF_X        25559040L
#define OFF_H2       29753344L
#define OFF_GU       33947648L
#define OFF_ACT      67502080L
#define OFF_MLP      84279296L
#define OFF_SCORES   88473600L
#define SCRATCH_FLOATS 155582464L

__device__ float g_scratch[SCRATCH_FLOATS];

__device__ __forceinline__ uint32_t f2tf32(float f) {
    uint32_t u;
    asm("cvt.rna.tf32.f32 %0, %1;" : "=r"(u) : "f"(f));
    return u;
}

// ---------------- reductions ----------------
__device__ __forceinline__ float warp_sum(float v) {
    #pragma unroll
    for (int o = 16; o > 0; o >>= 1) v += __shfl_xor_sync(0xffffffffu, v, o);
    return v;
}
__device__ __forceinline__ float warp_max(float v) {
    #pragma unroll
    for (int o = 16; o > 0; o >>= 1) v = fmaxf(v, __shfl_xor_sync(0xffffffffu, v, o));
    return v;
}
__device__ float block_sum(float v) {
    __shared__ float sh[32];
    int lane = threadIdx.x & 31, wid = threadIdx.x >> 5, nw = (blockDim.x + 31) >> 5;
    v = warp_sum(v);
    __syncthreads();
    if (lane == 0) sh[wid] = v;
    __syncthreads();
    if (wid == 0) {
        float x = (lane < nw) ? sh[lane] : 0.f;
        x = warp_sum(x);
        if (lane == 0) sh[0] = x;
    }
    __syncthreads();
    return sh[0];
}
__device__ float block_max(float v) {
    __shared__ float sh[32];
    int lane = threadIdx.x & 31, wid = threadIdx.x >> 5, nw = (blockDim.x + 31) >> 5;
    v = warp_max(v);
    __syncthreads();
    if (lane == 0) sh[wid] = v;
    __syncthreads();
    if (wid == 0) {
        float x = (lane < nw) ? sh[lane] : -3.4e38f;
        x = warp_max(x);
        if (lane == 0) sh[0] = x;
    }
    __syncthreads();
    return sh[0];
}

// ---------------- elementwise / norm kernels ----------------
__global__ void rms_kernel(const float* __restrict__ in, const float* __restrict__ res,
                           const float* __restrict__ w, float* __restrict__ out, int N) {
    int row = blockIdx.x;
    const float* x = in + (long)row * N;
    float sq = 0.f;
    for (int i = threadIdx.x; i < N; i += blockDim.x) { float v = x[i]; sq += v * v; }
    sq = block_sum(sq);
    float scale = rsqrtf(sq / (float)N + 1e-6f);
    float* o = out + (long)row * N;
    const float* r = res ? res + (long)row * N : nullptr;
    for (int i = threadIdx.x; i < N; i += blockDim.x)
        o[i] = (r ? r[i] : 0.f) + x[i] * scale * w[i];
}

__global__ void ln_kernel(const float* __restrict__ in, const float* __restrict__ s,
                          const float* __restrict__ b, float* __restrict__ out,
                          int N, int ldin, int ldout) {
    int row = blockIdx.x;
    const float* x = in + (long)row * ldin;
    float sum = 0.f, sq = 0.f;
    for (int i = threadIdx.x; i < N; i += blockDim.x) { float v = x[i]; sum += v; sq += v * v; }
    sum = block_sum(sum);
    sq = block_sum(sq);
    float m = sum / (float)N;
    float var = sq / (float)N - m * m;
    float r = rsqrtf(var + 1e-6f);
    float* o = out + (long)row * ldout;
    for (int i = threadIdx.x; i < N; i += blockDim.x)
        o[i] = (x[i] - m) * r * s[i] + b[i];
}

__global__ void rope_q_kernel(float* __restrict__ q, const int* __restrict__ pos) {
    int srow = blockIdx.x;
    int t = threadIdx.x;
    int h = t >> 5, j = t & 31;
    float p = (float)pos[srow];
    float invf = expf(-((float)(2 * j)) / 64.f * 9.210340371976184f);
    float sn, c;
    sincosf(p * invf, &sn, &c);
    long base = (long)srow * HQH_ + h * QH_ + NOPE_;
    float x1 = q[base + j], x2 = q[base + 32 + j];
    q[base + j]      = x1 * c - x2 * sn;
    q[base + 32 + j] = x2 * c + x1 * sn;
}

__global__ void rope_k_kernel(const float* __restrict__ ckv, const float* __restrict__ kv,
                              const int* __restrict__ pos, float* __restrict__ kf) {
    int srow = blockIdx.x;
    int t = threadIdx.x;
    if (t < 128) {
        kf[(long)srow * KFD_ + t] = kv[(long)srow * KVOUT_ + t];
    } else if (t < 160) {
        int j = t - 128;
        float p = (float)pos[srow];
        float invf = expf(-((float)(2 * j)) / 64.f * 9.210340371976184f);
        float sn, c;
        sincosf(p * invf, &sn, &c);
        const float* kp = ckv + (long)srow * CKV_ + KVL_;
        float x1 = kp[j], x2 = kp[32 + j];
        kf[(long)srow * KFD_ + 128 + j] = x1 * c - x2 * sn;
        kf[(long)srow * KFD_ + 160 + j] = x2 * c + x1 * sn;
    }
}

__global__ void transpose_kf_kernel(const float* __restrict__ kf, float* __restrict__ kfT) {
    int idx = blockIdx.x * blockDim.x + threadIdx.x;
    if (idx < S_ * KFD_) {
        int srow = idx / KFD_, d = idx % KFD_;
        kfT[(long)d * S_ + srow] = kf[idx];
    }
}

__global__ void softmax_kernel(float* __restrict__ scores) {
    int q = blockIdx.x, h = blockIdx.y;
    float* row = scores + ((long)h * S_ + q) * S_;
    float mx = -3.4e38f;
    for (int k = threadIdx.x; k <= q; k += blockDim.x)
        mx = fmaxf(mx, row[k]);
    mx = block_max(mx);
    float sum = 0.f;
    for (int k = threadIdx.x; k < S_; k += blockDim.x) {
        float e = (k <= q) ? expf(row[k] - mx) : 0.f;
        row[k] = e;
        sum += e;
    }
    sum = block_sum(sum);
    float inv = 1.f / sum;
    for (int k = threadIdx.x; k <= q; k += blockDim.x) row[k] *= inv;
}

__global__ void silu_mul_kernel(const float* __restrict__ gu, float* __restrict__ act) {
    long idx = (long)blockIdx.x * blockDim.x + threadIdx.x;
    int srow = (int)(idx >> 13);
    int i = (int)(idx & 8191);
    float g = gu[(long)srow * (2 * INTER_) + i];
    float u = gu[(long)srow * (2 * INTER_) + INTER_ + i];
    act[idx] = u * g / (1.f + expf(-g));
}

// ---------------- TF32 tensor-core GEMM, fragment-double-buffered ----------
// C = alpha * A @ B.  CTA 128x128x32, 256 threads = 8 warps (2m x 4n),
// warp tile 64x32, 3-stage cp.async ring, register ping-pong fragments.
// mode: 0 normal, 1 causal tile-skip (scores), 2 K-cut at diagonal (PV).
__device__ __forceinline__ void cp_async16(uint32_t dst, const void* src, int szbytes) {
    asm volatile("cp.async.cg.shared.global [%0], [%1], 16, %2;\n"
                 :: "r"(dst), "l"(src), "r"(szbytes));
}

#define AS_STRIDE 36     // 36 mod 32 = 4  -> A frag banks 4g+tg distinct
#define BS_STRIDE 136    // 136 mod 32 = 8 -> B frag banks 8tg+g distinct
#define A_STAGE (128 * AS_STRIDE)
#define B_STAGE (32 * BS_STRIDE)
#define NSTAGE 3
#define GEMM_SMEM_BYTES (NSTAGE * (A_STAGE + B_STAGE) * 4)

__global__ __launch_bounds__(256) void tf32gemm_kernel(
    const float* __restrict__ A, const float* __restrict__ B, float* __restrict__ C,
    int M, int N, int K, int lda, int ldb, int ldc,
    long strideA, long strideB, long strideC, float alpha, int mode)
{
    const int bm = blockIdx.y * 128;
    const int bn = blockIdx.x * 128;
    if (mode == 1 && bn >= bm + 128) return;          // causal: tile fully masked

    A += (long)blockIdx.z * strideA;
    B += (long)blockIdx.z * strideB;
    C += (long)blockIdx.z * strideC;

    int ntiles = K >> 5;
    if (mode == 2) { int ke = (bm + 159) >> 5; if (ke < ntiles) ntiles = ke; }

    extern __shared__ float smemf[];
    float* AsF = smemf;                       // [NSTAGE][128][36]
    float* BsF = smemf + NSTAGE * A_STAGE;    // [NSTAGE][32][136]
    uint32_t as_base = (uint32_t)__cvta_generic_to_shared(AsF);
    uint32_t bs_base = (uint32_t)__cvta_generic_to_shared(BsF);

    const int t = threadIdx.x;
    const int warp = t >> 5;
    const int lane = t & 31;
    const int g  = lane >> 2;
    const int tg = lane & 3;
    const int wm = (warp & 1) * 64;
    const int wn = (warp >> 1) * 32;

    // staging coords: 4 float4 chunks each for A and B per K-tile (256 thr)
    const int a_row0 = t >> 3;            // + 32*it
    const int a_c4   = (t & 7) * 4;
    const int b_row0 = t >> 5;            // + 8*it
    const int b_c4   = (t & 31) * 4;

    float acc[4][4][4];
    #pragma unroll
    for (int i = 0; i < 4; i++)
        #pragma unroll
        for (int j = 0; j < 4; j++)
            #pragma unroll
            for (int r = 0; r < 4; r++) acc[i][j][r] = 0.f;

    auto stage = [&](int kt) {
        int s = kt % NSTAGE;
        int k0 = kt << 5;
        uint32_t aoff = as_base + (uint32_t)(s * A_STAGE) * 4u;
        #pragma unroll
        for (int it = 0; it < 4; it++) {
            int row = a_row0 + 32 * it;
            cp_async16(aoff + (uint32_t)(row * AS_STRIDE + a_c4) * 4u,
                       A + (long)(bm + row) * lda + k0 + a_c4, 16);
        }
        uint32_t boff = bs_base + (uint32_t)(s * B_STAGE) * 4u;
        #pragma unroll
        for (int it = 0; it < 4; it++) {
            int row = b_row0 + 8 * it;
            int col = bn + b_c4;
            int sz = (col < N) ? 16 : 0;
            cp_async16(boff + (uint32_t)(row * BS_STRIDE + b_c4) * 4u,
                       B + (long)(k0 + row) * ldb + col, sz);
        }
    };

    stage(0);
    asm volatile("cp.async.commit_group;\n");
    stage(1);
    asm volatile("cp.async.commit_group;\n");

    uint32_t af[2][4][4], bf[2][4][2];

    for (int kt = 0; kt < ntiles; kt++) {
        asm volatile("cp.async.wait_group 1;\n");
        __syncthreads();

        const uint32_t* As = (const uint32_t*)(AsF + (kt % NSTAGE) * A_STAGE);
        const uint32_t* Bs = (const uint32_t*)(BsF + (kt % NSTAGE) * B_STAGE);

        // load fragments for kk=0 into buffer 0
        #pragma unroll
        for (int i = 0; i < 4; i++) {
            int r0 = wm + 16 * i + g;
            af[0][i][0] = f2tf32(__uint_as_float(As[(r0)     * AS_STRIDE + tg]));
            af[0][i][1] = f2tf32(__uint_as_float(As[(r0 + 8) * AS_STRIDE + tg]));
            af[0][i][2] = f2tf32(__uint_as_float(As[(r0)     * AS_STRIDE + tg + 4]));
            af[0][i][3] = f2tf32(__uint_as_float(As[(r0 + 8) * AS_STRIDE + tg + 4]));
        }
        #pragma unroll
        for (int j = 0; j < 4; j++) {
            int c0 = wn + 8 * j + g;
            bf[0][j][0] = f2tf32(__uint_as_float(Bs[(tg)     * BS_STRIDE + c0]));
            bf[0][j][1] = f2tf32(__uint_as_float(Bs[(tg + 4) * BS_STRIDE + c0]));
        }

        #pragma unroll
        for (int s4 = 0; s4 < 4; s4++) {
            const int cur = s4 & 1, nxt = cur ^ 1;
            if (s4 < 3) {
                int kk = (s4 + 1) * 8;
                #pragma unroll
                for (int i = 0; i < 4; i++) {
                    int r0 = wm + 16 * i + g;
                    af[nxt][i][0] = f2tf32(__uint_as_float(As[(r0)     * AS_STRIDE + kk + tg]));
                    af[nxt][i][1] = f2tf32(__uint_as_float(As[(r0 + 8) * AS_STRIDE + kk + tg]));
                    af[nxt][i][2] = f2tf32(__uint_as_float(As[(r0)     * AS_STRIDE + kk + tg + 4]));
                    af[nxt][i][3] = f2tf32(__uint_as_float(As[(r0 + 8) * AS_STRIDE + kk + tg + 4]));
                }
                #pragma unroll
                for (int j = 0; j < 4; j++) {
                    int c0 = wn + 8 * j + g;
                    bf[nxt][j][0] = f2tf32(__uint_as_float(Bs[(kk + tg)     * BS_STRIDE + c0]));
                    bf[nxt][j][1] = f2tf32(__uint_as_float(Bs[(kk + tg + 4) * BS_STRIDE + c0]));
                }
            }
            #pragma unroll
            for (int i = 0; i < 4; i++)
                #pragma unroll
                for (int j = 0; j < 4; j++) {
                    asm volatile(
                        "mma.sync.aligned.m16n8k8.row.col.f32.tf32.tf32.f32 "
                        "{%0,%1,%2,%3}, {%4,%5,%6,%7}, {%8,%9}, {%0,%1,%2,%3};\n"
                        : "+f"(acc[i][j][0]), "+f"(acc[i][j][1]),
                          "+f"(acc[i][j][2]), "+f"(acc[i][j][3])
                        : "r"(af[cur][i][0]), "r"(af[cur][i][1]),
                          "r"(af[cur][i][2]), "r"(af[cur][i][3]),
                          "r"(bf[cur][j][0]), "r"(bf[cur][j][1]));
                }
        }
        __syncthreads();
        if (kt + 2 < ntiles) stage(kt + 2);
        asm volatile("cp.async.commit_group;\n");
    }

    #pragma unroll
    for (int i = 0; i < 4; i++) {
        #pragma unroll
        for (int j = 0; j < 4; j++) {
            int r0 = bm + wm + 16 * i + g;
            int c0 = bn + wn + 8 * j + 2 * tg;
            if (c0 < N) {
                float2 v0 = make_float2(acc[i][j][0] * alpha, acc[i][j][1] * alpha);
                float2 v1 = make_float2(acc[i][j][2] * alpha, acc[i][j][3] * alpha);
                *(float2*)(C + (long)r0 * ldc + c0)       = v0;
                *(float2*)(C + (long)(r0 + 8) * ldc + c0) = v1;
            }
        }
    }
}

static inline void launch_gemm(const float* A, const float* B, float* C,
                               int M, int N, int K, int lda, int ldb, int ldc,
                               long sA, long sB, long sC, float alpha, int batch, int mode) {
    static bool attr_set = false;
    if (!attr_set) {
        cudaFuncSetAttribute(tf32gemm_kernel,
                             cudaFuncAttributeMaxDynamicSharedMemorySize, GEMM_SMEM_BYTES);
        attr_set = true;
    }
    dim3 grid((N + 127) / 128, M / 128, batch);
    tf32gemm_kernel<<<grid, 256, GEMM_SMEM_BYTES>>>(A, B, C, M, N, K, lda, ldb, ldc,
                                                    sA, sB, sC, alpha, mode);
}

// ---------------- entry ----------------
extern "C" void kernel_launch(void* const* d_in, const int* in_sizes, int n_in,
                              void* d_out, int out_size) {
    const float* hidden      = (const float*)d_in[0];
    // d_in[1] attention_mask: all-ones; unused (pure causal).
    const int*   pos         = (const int*)d_in[2];
    const float* w_in        = (const float*)d_in[3];
    const float* w_post_attn = (const float*)d_in[4];
    const float* w_pre_ff    = (const float*)d_in[5];
    const float* w_post_ff   = (const float*)d_in[6];
    const float* qa_w        = (const float*)d_in[7];
    const float* qa_ln_s     = (const float*)d_in[8];
    const float* qa_ln_b     = (const float*)d_in[9];
    const float* qb_w        = (const float*)d_in[10];
    const float* kv_mqa_w    = (const float*)d_in[11];
    const float* kv_ln_s     = (const float*)d_in[12];
    const float* kv_ln_b     = (const float*)d_in[13];
    const float* kvi_w       = (const float*)d_in[14];
    const float* o_w         = (const float*)d_in[15];
    const float* gate_up_w   = (const float*)d_in[16];
    const float* down_w      = (const float*)d_in[17];
    float* out = (float*)d_out;

    float* sc = nullptr;
    cudaGetSymbolAddress((void**)&sc, g_scratch);
    float* h1       = sc + OFF_H1;
    float* qa       = sc + OFF_QA;
    float* q        = sc + OFF_Q;
    float* ckv      = sc + OFF_CKV;
    float* kvln     = sc + OFF_KVLN;
    float* kv       = sc + OFF_KV;
    float* kf       = sc + OFF_KF;
    float* kfT      = sc + OFF_KFT;
    float* attno    = sc + OFF_ATTNO;
    float* attnproj = sc + OFF_ATTNPROJ;
    float* x        = sc + OFF_X;
    float* h2       = sc + OFF_H2;
    float* gu       = sc + OFF_GU;
    float* act      = sc + OFF_ACT;
    float* mlp      = sc + OFF_MLP;
    float* scores   = sc + OFF_SCORES;

    rms_kernel<<<S_, 256>>>(hidden, nullptr, w_in, h1, HID_);

    launch_gemm(h1, qa_w, qa, S_, QL_, HID_, HID_, QL_, QL_, 0, 0, 0, 1.f, 1, 0);
    ln_kernel<<<S_, 256>>>(qa, qa_ln_s, qa_ln_b, qa, QL_, QL_, QL_);

    launch_gemm(qa, qb_w, q, S_, HQH_, QL_, QL_, HQH_, HQH_, 0, 0, 0, 1.f, 1, 0);

    launch_gemm(h1, kv_mqa_w, ckv, S_, CKV_, HID_, HID_, CKV_, CKV_, 0, 0, 0, 1.f, 1, 0);
    ln_kernel<<<S_, 256>>>(ckv, kv_ln_s, kv_ln_b, kvln, KVL_, CKV_, KVL_);

    launch_gemm(kvln, kvi_w, kv, S_, KVOUT_, KVL_, KVL_, H_ * (NOPE_ + VD_), KVOUT_, 0, 0, 0, 1.f, 1, 0);

    rope_q_kernel<<<S_, 512>>>(q, pos);
    rope_k_kernel<<<S_, 256>>>(ckv, kv, pos, kf);
    transpose_kf_kernel<<<(S_ * KFD_ + 255) / 256, 256>>>(kf, kfT);

    const float scale = 0.07216878364870323f;   // 192^-0.5
    launch_gemm(q, kfT, scores, S_, S_, KFD_, HQH_, S_, S_,
                (long)QH_, 0L, (long)S_ * S_, scale, H_, 1);

    softmax_kernel<<<dim3(S_, H_), 256>>>(scores);

    launch_gemm(scores, kv + NOPE_, attno, S_, VD_, S_, S_, KVOUT_, HID_,
                (long)S_ * S_, 0L, (long)VD_, 1.f, H_, 2);

    launch_gemm(attno, o_w, attnproj, S_, HID_, HID_, HID_, HID_, HID_, 0, 0, 0, 1.f, 1, 0);

    rms_kernel<<<S_, 256>>>(attnproj, hidden, w_post_attn, x, HID_);
    rms_kernel<<<S_, 256>>>(x, nullptr, w_pre_ff, h2, HID_);

    launch_gemm(h2, gate_up_w, gu, S_, 2 * INTER_, HID_, HID_, 2 * INTER_, 2 * INTER_, 0, 0, 0, 1.f, 1, 0);
    silu_mul_kernel<<<(S_ * INTER_) / 256, 256>>>(gu, act);

    launch_gemm(act, down_w, mlp, S_, HID_, INTER_, INTER_, HID_, HID_, 0, 0, 0, 1.f, 1, 0);

    rms_kernel<<<S_, 256>>>(mlp, x, w_post_ff, out, HID_);
}

// round 9
// speedup vs baseline: 1.7471x; 1.7471x over previous
#include <cuda_runtime.h>
#include <cuda_fp16.h>
#include <math.h>
#include <stdint.h>

// ---------------- problem constants ----------------
#define S_   2048
#define HID_ 2048
#define H_   16
#define NOPE_ 128
#define ROPE_ 64
#define VD_  128
#define QH_  192
#define QL_  1536
#define KVL_ 512
#define CKV_ 576
#define INTER_ 8192
#define HQH_ 3072
#define KVOUT_ 256
#define KFD_ 192

// ---------------- scratch byte offsets ----------------
#define OB_SCORES   0L            // fp32 [16][S][S]            268435456
#define OB_P        268435456L    // half [16][S][S]            134217728
#define OB_H1       402653184L    // half [S][2048]             8388608
#define OB_QA       411041792L    // half [S][1536]             6291456
#define OB_Q        417333248L    // half [S][3072]             12582912
#define OB_CKV      429916160L    // half [S][576]              2359296
#define OB_KVLN     432275456L    // half [S][512]              2097152
#define OB_KV       434372608L    // half [S][256]              1048576
#define OB_KFT      435421184L    // u32  [96][2048]            786432
#define OB_V2       436207616L    // u32  [1024][128]           524288
#define OB_ATTNO    436731904L    // half [S][2048]             8388608
#define OB_ATTNPROJ 445120512L    // fp32 [S][2048]             16777216
#define OB_X        461897728L    // fp32 [S][2048]             16777216
#define OB_H2       478674944L    // half [S][2048]             8388608
#define OB_GU       487063552L    // half [S][16384]            67108864
#define OB_ACT      554172416L    // half [S][8192]             33554432
#define OB_MLP      587726848L    // fp32 [S][2048]             16777216
#define OB_WQA      604504064L    // u32 [1024][1536]           6291456
#define OB_WQB      610795520L    // u32 [768][3072]            9437184
#define OB_WKV      620232704L    // u32 [1024][576]            2359296
#define OB_WKVI     622592000L    // u32 [256][256]             262144
#define OB_WO       622854144L    // u32 [1024][2048]           8388608
#define OB_WGU      631242752L    // u32 [1024][16384]          67108864
#define OB_WDN      698351616L    // u32 [4096][2048]           33554432
#define SCRATCH_BYTES 732000000L

__device__ __align__(256) unsigned char g_scratch[SCRATCH_BYTES];

__device__ __forceinline__ uint32_t pack_half2(float a, float b) {
    __half2 h = __floats2half2_rn(a, b);
    return *(uint32_t*)&h;
}

// ---------------- reductions ----------------
__device__ __forceinline__ float warp_sum(float v) {
    #pragma unroll
    for (int o = 16; o > 0; o >>= 1) v += __shfl_xor_sync(0xffffffffu, v, o);
    return v;
}
__device__ __forceinline__ float warp_max(float v) {
    #pragma unroll
    for (int o = 16; o > 0; o >>= 1) v = fmaxf(v, __shfl_xor_sync(0xffffffffu, v, o));
    return v;
}
__device__ float block_sum(float v) {
    __shared__ float sh[32];
    int lane = threadIdx.x & 31, wid = threadIdx.x >> 5, nw = (blockDim.x + 31) >> 5;
    v = warp_sum(v);
    __syncthreads();
    if (lane == 0) sh[wid] = v;
    __syncthreads();
    if (wid == 0) {
        float x = (lane < nw) ? sh[lane] : 0.f;
        x = warp_sum(x);
        if (lane == 0) sh[0] = x;
    }
    __syncthreads();
    return sh[0];
}
__device__ float block_max(float v) {
    __shared__ float sh[32];
    int lane = threadIdx.x & 31, wid = threadIdx.x >> 5, nw = (blockDim.x + 31) >> 5;
    v = warp_max(v);
    __syncthreads();
    if (lane == 0) sh[wid] = v;
    __syncthreads();
    if (wid == 0) {
        float x = (lane < nw) ? sh[lane] : -3.4e38f;
        x = warp_max(x);
        if (lane == 0) sh[0] = x;
    }
    __syncthreads();
    return sh[0];
}

// ---------------- weight conversion: fp32 [K][lds] -> interleaved half2 u32 [K/2][Nout]
__global__ void conv_w_kernel(const float* __restrict__ src, uint32_t* __restrict__ dst,
                              int K2, int Nout, int lds, int c0) {
    long i = (long)blockIdx.x * blockDim.x + threadIdx.x;
    long total = (long)K2 * (Nout >> 2);
    if (i >= total) return;
    int k2 = (int)(i / (Nout >> 2));
    int c  = (int)(i % (Nout >> 2)) << 2;
    float4 a = *(const float4*)(src + (long)(2 * k2) * lds + c0 + c);
    float4 b = *(const float4*)(src + (long)(2 * k2 + 1) * lds + c0 + c);
    uint4 o;
    o.x = pack_half2(a.x, b.x);
    o.y = pack_half2(a.y, b.y);
    o.z = pack_half2(a.z, b.z);
    o.w = pack_half2(a.w, b.w);
    *(uint4*)(dst + (long)k2 * Nout + c) = o;
}

// ---------------- elementwise / norm kernels ----------------
// rms: fp32 in (+optional fp32 residual) -> half or fp32 out
__global__ void rms_kernel(const float* __restrict__ in, const float* __restrict__ res,
                           const float* __restrict__ w, void* __restrict__ out,
                           int N, int outHalf) {
    int row = blockIdx.x;
    const float* x = in + (long)row * N;
    float sq = 0.f;
    for (int i = threadIdx.x; i < N; i += blockDim.x) { float v = x[i]; sq += v * v; }
    sq = block_sum(sq);
    float scale = rsqrtf(sq / (float)N + 1e-6f);
    const float* r = res ? res + (long)row * N : nullptr;
    if (outHalf) {
        __half* o = (__half*)out + (long)row * N;
        for (int i = threadIdx.x; i < N; i += blockDim.x)
            o[i] = __float2half_rn((r ? r[i] : 0.f) + x[i] * scale * w[i]);
    } else {
        float* o = (float*)out + (long)row * N;
        for (int i = threadIdx.x; i < N; i += blockDim.x)
            o[i] = (r ? r[i] : 0.f) + x[i] * scale * w[i];
    }
}

// layernorm: half in -> half out
__global__ void ln_kernel(const __half* __restrict__ in, const float* __restrict__ s,
                          const float* __restrict__ b, __half* __restrict__ out,
                          int N, int ldin, int ldout) {
    int row = blockIdx.x;
    const __half* x = in + (long)row * ldin;
    float sum = 0.f, sq = 0.f;
    for (int i = threadIdx.x; i < N; i += blockDim.x) {
        float v = __half2float(x[i]);
        sum += v; sq += v * v;
    }
    sum = block_sum(sum);
    sq = block_sum(sq);
    float m = sum / (float)N;
    float var = sq / (float)N - m * m;
    float r = rsqrtf(var + 1e-6f);
    __half* o = out + (long)row * ldout;
    for (int i = threadIdx.x; i < N; i += blockDim.x)
        o[i] = __float2half_rn((__half2float(x[i]) - m) * r * s[i] + b[i]);
}

// RoPE on q (half, in place)
__global__ void rope_q_kernel(__half* __restrict__ q, const int* __restrict__ pos) {
    int srow = blockIdx.x;
    int t = threadIdx.x;         // 512 = 16 heads * 32 freq
    int h = t >> 5, j = t & 31;
    float p = (float)pos[srow];
    float invf = expf(-((float)(2 * j)) / 64.f * 9.210340371976184f);
    float sn, c;
    sincosf(p * invf, &sn, &c);
    long base = (long)srow * HQH_ + h * QH_ + NOPE_;
    float x1 = __half2float(q[base + j]);
    float x2 = __half2float(q[base + 32 + j]);
    q[base + j]      = __float2half_rn(x1 * c - x2 * sn);
    q[base + 32 + j] = __float2half_rn(x2 * c + x1 * sn);
}

// build kfT interleaved: kfT2[k2][srow] u32 = (kf[srow][2k2], kf[srow][2k2+1])
__global__ void build_kft_kernel(const __half* __restrict__ kv, const __half* __restrict__ ckv,
                                 const int* __restrict__ pos, uint32_t* __restrict__ kft2) {
    int srow = blockIdx.x;
    int k2 = threadIdx.x;        // 0..95
    uint32_t val;
    if (k2 < 64) {
        // nope part: copy half pair directly from kv
        val = *(const uint32_t*)(kv + (long)srow * KVOUT_ + 2 * k2);
    } else {
        const __half* kp = ckv + (long)srow * CKV_ + KVL_;
        float p = (float)pos[srow];
        float v[2];
        #pragma unroll
        for (int u = 0; u < 2; u++) {
            int idx = 2 * k2 + u - 128;   // 0..63 within rope block
            int jj = (idx < 32) ? idx : idx - 32;
            float invf = expf(-((float)(2 * jj)) / 64.f * 9.210340371976184f);
            float sn, c;
            sincosf(p * invf, &sn, &c);
            float a = __half2float(kp[jj]);
            float b2 = __half2float(kp[jj + 32]);
            v[u] = (idx < 32) ? (a * c - b2 * sn) : (b2 * c + a * sn);
        }
        val = pack_half2(v[0], v[1]);
    }
    kft2[(long)k2 * S_ + srow] = val;
}

// V interleave: v2[k2][n] = (V[2k2][n], V[2k2+1][n]),  V = kv[:,128:256]
__global__ void build_v2_kernel(const __half* __restrict__ kv, uint32_t* __restrict__ v2) {
    int i = blockIdx.x * blockDim.x + threadIdx.x;   // 1024*128
    if (i >= (S_ / 2) * VD_) return;
    int k2 = i >> 7, n = i & 127;
    float a = __half2float(kv[(long)(2 * k2) * KVOUT_ + NOPE_ + n]);
    float b = __half2float(kv[(long)(2 * k2 + 1) * KVOUT_ + NOPE_ + n]);
    v2[i] = pack_half2(a, b);
}

// causal softmax: reads fp32 scores, writes half P (zeros above diagonal)
__global__ void softmax_kernel(const float* __restrict__ scores, __half* __restrict__ P) {
    int q = blockIdx.x, h = blockIdx.y;
    const float* row = scores + ((long)h * S_ + q) * S_;
    __half* prow = P + ((long)h * S_ + q) * S_;
    float mx = -3.4e38f;
    for (int k = threadIdx.x; k <= q; k += blockDim.x)
        mx = fmaxf(mx, row[k]);
    mx = block_max(mx);
    float sum = 0.f;
    for (int k = threadIdx.x; k <= q; k += blockDim.x)
        sum += expf(row[k] - mx);
    sum = block_sum(sum);
    float inv = 1.f / sum;
    for (int k = threadIdx.x; k < S_; k += blockDim.x)
        prow[k] = __float2half_rn((k <= q) ? expf(row[k] - mx) * inv : 0.f);
}

__global__ void silu_mul_kernel(const __half* __restrict__ gu, __half* __restrict__ act) {
    long idx = (long)blockIdx.x * blockDim.x + threadIdx.x;
    int srow = (int)(idx >> 13);
    int i = (int)(idx & 8191);
    float g = __half2float(gu[(long)srow * (2 * INTER_) + i]);
    float u = __half2float(gu[(long)srow * (2 * INTER_) + INTER_ + i]);
    act[idx] = __float2half_rn(u * g / (1.f + expf(-g)));
}

// ---------------- FP16 tensor-core GEMM (m16n8k16, fp32 accum) ----------------
// C = alpha * A @ B. A: half [M][lda] row-major. B2: u32 [K/2][ldb2] interleaved
// half2 pairs (B[2k2][n], B[2k2+1][n]). CTA 128x128x32, 128 threads = 4 warps
// (2m x 2n), warp tile 64x64. 3-stage cp.async.
// mode: 0 normal, 1 causal tile-skip, 2 K-cut at diagonal.
__device__ __forceinline__ void cp_async16(uint32_t dst, const void* src, int szbytes) {
    asm volatile("cp.async.cg.shared.global [%0], [%1], 16, %2;\n"
                 :: "r"(dst), "l"(src), "r"(szbytes));
}

#define A_STRIDE_U32 20      // 40 halves per row (32 data + 8 pad) = 20 u32
#define B_STRIDE_U32 136     // 128 data + 8 pad
#define A_STAGE_B (128 * 80)         // 10240 bytes
#define B_STAGE_B (16 * 544)         // 8704 bytes
#define NSTAGE 3
#define GEMM_SMEM_BYTES (NSTAGE * (A_STAGE_B + B_STAGE_B))   // 56832

__global__ __launch_bounds__(128) void h16gemm_kernel(
    const __half* __restrict__ A, const uint32_t* __restrict__ B2, void* __restrict__ Cv,
    int M, int N, int K, int lda, int ldb2, int ldc,
    long sA, long sB2, long sC, float alpha, int outHalf, int mode)
{
    const int bm = blockIdx.y * 128;
    const int bn = blockIdx.x * 128;
    if (mode == 1 && bn >= bm + 128) return;          // causal: tile fully masked

    A  += (long)blockIdx.z * sA;
    B2 += (long)blockIdx.z * sB2;
    char* Cb = (char*)Cv + (long)blockIdx.z * sC * (outHalf ? 2 : 4);

    int ntiles = K >> 5;
    if (mode == 2) { int ke = (bm + 159) >> 5; if (ke < ntiles) ntiles = ke; }

    extern __shared__ __align__(16) char smem[];
    uint32_t smem_base = (uint32_t)__cvta_generic_to_shared(smem);
    const uint32_t a_base = smem_base;
    const uint32_t b_base = smem_base + NSTAGE * A_STAGE_B;

    const int t = threadIdx.x;
    const int warp = t >> 5;
    const int lane = t & 31;
    const int g  = lane >> 2;
    const int tg = lane & 3;
    const int wm = (warp & 1) * 64;
    const int wn = (warp >> 1) * 64;

    float acc[4][8][4];
    #pragma unroll
    for (int i = 0; i < 4; i++)
        #pragma unroll
        for (int j = 0; j < 8; j++)
            #pragma unroll
            for (int r = 0; r < 4; r++) acc[i][j][r] = 0.f;

    // staging: A 512 chunks (row, 4x16B), B 512 chunks (16 rows x 32x16B)
    auto stage = [&](int kt) {
        int s = kt % NSTAGE;
        int k0 = kt << 5;           // k offset in halves
        uint32_t ao = a_base + (uint32_t)s * A_STAGE_B;
        #pragma unroll
        for (int it = 0; it < 4; it++) {
            int idx = t + 128 * it;
            int row = idx >> 2;
            int c   = idx & 3;       // 16B chunk (8 halves)
            cp_async16(ao + (uint32_t)(row * 80 + c * 16),
                       A + (long)(bm + row) * lda + k0 + c * 8, 16);
        }
        uint32_t bo = b_base + (uint32_t)s * B_STAGE_B;
        int k20 = kt << 4;          // k-pair row offset
        #pragma unroll
        for (int it = 0; it < 4; it++) {
            int idx = t + 128 * it;
            int row = idx >> 5;          // 0..15
            int c4  = (idx & 31) * 4;    // u32 col
            int col = bn + c4;
            int sz = (col < N) ? 16 : 0;
            cp_async16(bo + (uint32_t)(row * 544 + c4 * 4),
                       B2 + (long)(k20 + row) * ldb2 + col, sz);
        }
    };

    stage(0);
    asm volatile("cp.async.commit_group;\n");
    stage(1);
    asm volatile("cp.async.commit_group;\n");

    for (int kt = 0; kt < ntiles; kt++) {
        asm volatile("cp.async.wait_group 1;\n");
        __syncthreads();

        const uint32_t* As = (const uint32_t*)(smem + (kt % NSTAGE) * A_STAGE_B);
        const uint32_t* Bs = (const uint32_t*)(smem + NSTAGE * A_STAGE_B + (kt % NSTAGE) * B_STAGE_B);

        #pragma unroll
        for (int kk2 = 0; kk2 < 16; kk2 += 8) {      // two k16 steps
            uint32_t af[4][4];
            #pragma unroll
            for (int i = 0; i < 4; i++) {
                int r0 = wm + 16 * i + g;
                af[i][0] = As[(r0)     * A_STRIDE_U32 + kk2 + tg];
                af[i][1] = As[(r0 + 8) * A_STRIDE_U32 + kk2 + tg];
                af[i][2] = As[(r0)     * A_STRIDE_U32 + kk2 + tg + 4];
                af[i][3] = As[(r0 + 8) * A_STRIDE_U32 + kk2 + tg + 4];
            }
            uint32_t bf[8][2];
            #pragma unroll
            for (int j = 0; j < 8; j++) {
                int c0 = wn + 8 * j + g;
                bf[j][0] = Bs[(kk2 + tg)     * B_STRIDE_U32 + c0];
                bf[j][1] = Bs[(kk2 + tg + 4) * B_STRIDE_U32 + c0];
            }
            #pragma unroll
            for (int i = 0; i < 4; i++)
                #pragma unroll
                for (int j = 0; j < 8; j++) {
                    asm volatile(
                        "mma.sync.aligned.m16n8k16.row.col.f32.f16.f16.f32 "
                        "{%0,%1,%2,%3}, {%4,%5,%6,%7}, {%8,%9}, {%0,%1,%2,%3};\n"
                        : "+f"(acc[i][j][0]), "+f"(acc[i][j][1]),
                          "+f"(acc[i][j][2]), "+f"(acc[i][j][3])
                        : "r"(af[i][0]), "r"(af[i][1]), "r"(af[i][2]), "r"(af[i][3]),
                          "r"(bf[j][0]), "r"(bf[j][1]));
                }
        }
        __syncthreads();
        if (kt + 2 < ntiles) stage(kt + 2);
        asm volatile("cp.async.commit_group;\n");
    }

    // epilogue
    if (outHalf) {
        __half* C = (__half*)Cb;
        #pragma unroll
        for (int i = 0; i < 4; i++)
            #pragma unroll
            for (int j = 0; j < 8; j++) {
                int r0 = bm + wm + 16 * i + g;
                int c0 = bn + wn + 8 * j + 2 * tg;
                if (c0 < N) {
                    *(uint32_t*)(C + (long)r0 * ldc + c0) =
                        pack_half2(acc[i][j][0] * alpha, acc[i][j][1] * alpha);
                    *(uint32_t*)(C + (long)(r0 + 8) * ldc + c0) =
                        pack_half2(acc[i][j][2] * alpha, acc[i][j][3] * alpha);
                }
            }
    } else {
        float* C = (float*)Cb;
        #pragma unroll
        for (int i = 0; i < 4; i++)
            #pragma unroll
            for (int j = 0; j < 8; j++) {
                int r0 = bm + wm + 16 * i + g;
                int c0 = bn + wn + 8 * j + 2 * tg;
                if (c0 < N) {
                    *(float2*)(C + (long)r0 * ldc + c0) =
                        make_float2(acc[i][j][0] * alpha, acc[i][j][1] * alpha);
                    *(float2*)(C + (long)(r0 + 8) * ldc + c0) =
                        make_float2(acc[i][j][2] * alpha, acc[i][j][3] * alpha);
                }
            }
    }
}

static inline void launch_gemm(const __half* A, const uint32_t* B2, void* C,
                               int M, int N, int K, int lda, int ldb2, int ldc,
                               long sA, long sB2, long sC, float alpha, int batch,
                               int outHalf, int mode) {
    static bool attr_set = false;
    if (!attr_set) {
        cudaFuncSetAttribute(h16gemm_kernel,
                             cudaFuncAttributeMaxDynamicSharedMemorySize, GEMM_SMEM_BYTES);
        attr_set = true;
    }
    dim3 grid((N + 127) / 128, M / 128, batch);
    h16gemm_kernel<<<grid, 128, GEMM_SMEM_BYTES>>>(A, B2, C, M, N, K, lda, ldb2, ldc,
                                                   sA, sB2, sC, alpha, outHalf, mode);
}

// ---------------- entry ----------------
extern "C" void kernel_launch(void* const* d_in, const int* in_sizes, int n_in,
                              void* d_out, int out_size) {
    const float* hidden      = (const float*)d_in[0];
    // d_in[1] attention_mask: all-ones; unused (pure causal).
    const int*   pos         = (const int*)d_in[2];
    const float* w_in        = (const float*)d_in[3];
    const float* w_post_attn = (const float*)d_in[4];
    const float* w_pre_ff    = (const float*)d_in[5];
    const float* w_post_ff   = (const float*)d_in[6];
    const float* qa_w        = (const float*)d_in[7];
    const float* qa_ln_s     = (const float*)d_in[8];
    const float* qa_ln_b     = (const float*)d_in[9];
    const float* qb_w        = (const float*)d_in[10];
    const float* kv_mqa_w    = (const float*)d_in[11];
    const float* kv_ln_s     = (const float*)d_in[12];
    const float* kv_ln_b     = (const float*)d_in[13];
    const float* kvi_w       = (const float*)d_in[14];
    const float* o_w         = (const float*)d_in[15];
    const float* gate_up_w   = (const float*)d_in[16];
    const float* down_w      = (const float*)d_in[17];
    float* out = (float*)d_out;

    unsigned char* sc = nullptr;
    cudaGetSymbolAddress((void**)&sc, g_scratch);
    float*    scoresF = (float*)(sc + OB_SCORES);
    __half*   Ph      = (__half*)(sc + OB_P);
    __half*   h1h     = (__half*)(sc + OB_H1);
    __half*   qah     = (__half*)(sc + OB_QA);
    __half*   qh      = (__half*)(sc + OB_Q);
    __half*   ckvh    = (__half*)(sc + OB_CKV);
    __half*   kvlnh   = (__half*)(sc + OB_KVLN);
    __half*   kvh     = (__half*)(sc + OB_KV);
    uint32_t* kft2    = (uint32_t*)(sc + OB_KFT);
    uint32_t* v2      = (uint32_t*)(sc + OB_V2);
    __half*   attnoh  = (__half*)(sc + OB_ATTNO);
    float*    attnprojF = (float*)(sc + OB_ATTNPROJ);
    float*    xF      = (float*)(sc + OB_X);
    __half*   h2h     = (__half*)(sc + OB_H2);
    __half*   guh     = (__half*)(sc + OB_GU);
    __half*   acth    = (__half*)(sc + OB_ACT);
    float*    mlpF    = (float*)(sc + OB_MLP);
    uint32_t* Wqa = (uint32_t*)(sc + OB_WQA);
    uint32_t* Wqb = (uint32_t*)(sc + OB_WQB);
    uint32_t* Wkv = (uint32_t*)(sc + OB_WKV);
    uint32_t* Wkvi = (uint32_t*)(sc + OB_WKVI);
    uint32_t* Wo  = (uint32_t*)(sc + OB_WO);
    uint32_t* Wgu = (uint32_t*)(sc + OB_WGU);
    uint32_t* Wdn = (uint32_t*)(sc + OB_WDN);

    // ---- one-time weight conversions (idempotent, graph-capturable) ----
    auto cw = [&](const float* s, uint32_t* d, int K, int Nout, int lds, int c0) {
        long total = (long)(K / 2) * (Nout / 4);
        conv_w_kernel<<<(int)((total + 255) / 256), 256>>>(s, d, K / 2, Nout, lds, c0);
    };
    cw(qa_w,      Wqa,  HID_, QL_,        QL_,              0);
    cw(qb_w,      Wqb,  QL_,  HQH_,       HQH_,             0);
    cw(kv_mqa_w,  Wkv,  HID_, CKV_,       CKV_,             0);
    cw(kvi_w,     Wkvi, KVL_, KVOUT_,     H_ * (NOPE_+VD_), 0);
    cw(o_w,       Wo,   HID_, HID_,       HID_,             0);
    cw(gate_up_w, Wgu,  HID_, 2 * INTER_, 2 * INTER_,       0);
    cw(down_w,    Wdn,  INTER_, HID_,     HID_,             0);

    // 1. h1 = rms(hidden)*w_in  -> half
    rms_kernel<<<S_, 256>>>(hidden, nullptr, w_in, h1h, HID_, 1);

    // 2-3. qa = h1 @ qa_w (half) ; LN in place
    launch_gemm(h1h, Wqa, qah, S_, QL_, HID_, HID_, QL_, QL_, 0, 0, 0, 1.f, 1, 1, 0);
    ln_kernel<<<S_, 256>>>(qah, qa_ln_s, qa_ln_b, qah, QL_, QL_, QL_);

    // 4. q = qa @ qb_w (half)
    launch_gemm(qah, Wqb, qh, S_, HQH_, QL_, QL_, HQH_, HQH_, 0, 0, 0, 1.f, 1, 1, 0);

    // 5-6. ckv = h1 @ kv_mqa_w (half) ; LN -> kvln
    launch_gemm(h1h, Wkv, ckvh, S_, CKV_, HID_, HID_, CKV_, CKV_, 0, 0, 0, 1.f, 1, 1, 0);
    ln_kernel<<<S_, 256>>>(ckvh, kv_ln_s, kv_ln_b, kvlnh, KVL_, CKV_, KVL_);

    // 7. kv = kvln @ kvi_w[:, :256] (half)
    launch_gemm(kvlnh, Wkvi, kvh, S_, KVOUT_, KVL_, KVL_, KVOUT_, KVOUT_, 0, 0, 0, 1.f, 1, 1, 0);

    // 8-10. RoPE q (in place), build kfT2, build V2
    rope_q_kernel<<<S_, 512>>>(qh, pos);
    build_kft_kernel<<<S_, 96>>>(kvh, ckvh, pos, kft2);
    build_v2_kernel<<<(S_ / 2 * VD_ + 255) / 256, 256>>>(kvh, v2);

    // 11. scores = scale * q_h @ kf^T  (fp32 out, causal tile skip)
    const float scale = 0.07216878364870323f;   // 192^-0.5
    launch_gemm(qh, kft2, scoresF, S_, S_, KFD_, HQH_, S_, S_,
                (long)QH_, 0L, (long)S_ * S_, scale, H_, 0, 1);

    // 12. softmax -> half P (zero-filled above diagonal)
    softmax_kernel<<<dim3(S_, H_), 256>>>(scoresF, Ph);

    // 13. attno[:, h*128:] = P_h @ V (half out, K-cut)
    launch_gemm(Ph, v2, attnoh, S_, VD_, S_, S_, VD_, HID_,
                (long)S_ * S_, 0L, (long)VD_, 1.f, H_, 1, 2);

    // 14. attnproj = attno @ o_w (fp32 out)
    launch_gemm(attnoh, Wo, attnprojF, S_, HID_, HID_, HID_, HID_, HID_, 0, 0, 0, 1.f, 1, 0, 0);

    // 15-16. residual + norms
    rms_kernel<<<S_, 256>>>(attnprojF, hidden, w_post_attn, xF, HID_, 0);
    rms_kernel<<<S_, 256>>>(xF, nullptr, w_pre_ff, h2h, HID_, 1);

    // 17-18. gate_up (half) + silu
    launch_gemm(h2h, Wgu, guh, S_, 2 * INTER_, HID_, HID_, 2 * INTER_, 2 * INTER_, 0, 0, 0, 1.f, 1, 1, 0);
    silu_mul_kernel<<<(S_ * INTER_) / 256, 256>>>(guh, acth);

    // 19. down (fp32 out)
    launch_gemm(acth, Wdn, mlpF, S_, HID_, INTER_, INTER_, HID_, HID_, 0, 0, 0, 1.f, 1, 0, 0);

    // 20. out = x + rms(mlp)*w_post_ff (fp32)
    rms_kernel<<<S_, 256>>>(mlpF, xF, w_post_ff, out, HID_, 0);
}

// round 10
// speedup vs baseline: 1.7610x; 1.0079x over previous
#include <cuda_runtime.h>
#include <cuda_fp16.h>
#include <math.h>
#include <stdint.h>

// ---------------- problem constants ----------------
#define S_   2048
#define HID_ 2048
#define H_   16
#define NOPE_ 128
#define ROPE_ 64
#define VD_  128
#define QH_  192
#define QL_  1536
#define KVL_ 512
#define CKV_ 576
#define INTER_ 8192
#define HQH_ 3072
#define KVOUT_ 256
#define KFD_ 192

// ---------------- scratch byte offsets ----------------
#define OB_SCORES   0L            // fp32 [16][S][S]            268435456
#define OB_P        268435456L    // half [16][S][S]            134217728
#define OB_H1       402653184L    // half [S][2048]             8388608
#define OB_QA       411041792L    // half [S][1536]             6291456
#define OB_Q        417333248L    // half [S][3072]             12582912
#define OB_CKV      429916160L    // half [S][576]              2359296
#define OB_KVLN     432275456L    // half [S][512]              2097152
#define OB_KV       434372608L    // half [S][256]              1048576
#define OB_KFT      435421184L    // u32  [96][2048]            786432
#define OB_V2       436207616L    // u32  [1024][128]           524288
#define OB_ATTNO    436731904L    // half [S][2048]             8388608
#define OB_ATTNPROJ 445120512L    // fp32 [S][2048]             16777216
#define OB_X        461897728L    // fp32 [S][2048]             16777216
#define OB_H2       478674944L    // half [S][2048]             8388608
#define OB_GU       487063552L    // half [S][16384]            67108864
#define OB_ACT      554172416L    // half [S][8192]             33554432
#define OB_MLP      587726848L    // fp32 [S][2048]             16777216
#define OB_WQA      604504064L    // u32 [1024][1536]           6291456
#define OB_WQB      610795520L    // u32 [768][3072]            9437184
#define OB_WKV      620232704L    // u32 [1024][576]            2359296
#define OB_WKVI     622592000L    // u32 [256][256]             262144
#define OB_WO       622854144L    // u32 [1024][2048]           8388608
#define OB_WGU      631242752L    // u32 [1024][16384]          67108864
#define OB_WDN      698351616L    // u32 [4096][2048]           33554432
#define SCRATCH_BYTES 732000000L

__device__ __align__(256) unsigned char g_scratch[SCRATCH_BYTES];

__device__ __forceinline__ uint32_t pack_half2(float a, float b) {
    __half2 h = __floats2half2_rn(a, b);
    return *(uint32_t*)&h;
}

// ---------------- reductions ----------------
__device__ __forceinline__ float warp_sum(float v) {
    #pragma unroll
    for (int o = 16; o > 0; o >>= 1) v += __shfl_xor_sync(0xffffffffu, v, o);
    return v;
}
__device__ __forceinline__ float warp_max(float v) {
    #pragma unroll
    for (int o = 16; o > 0; o >>= 1) v = fmaxf(v, __shfl_xor_sync(0xffffffffu, v, o));
    return v;
}
__device__ float block_sum(float v) {
    __shared__ float sh[32];
    int lane = threadIdx.x & 31, wid = threadIdx.x >> 5, nw = (blockDim.x + 31) >> 5;
    v = warp_sum(v);
    __syncthreads();
    if (lane == 0) sh[wid] = v;
    __syncthreads();
    if (wid == 0) {
        float x = (lane < nw) ? sh[lane] : 0.f;
        x = warp_sum(x);
        if (lane == 0) sh[0] = x;
    }
    __syncthreads();
    return sh[0];
}
__device__ float block_max(float v) {
    __shared__ float sh[32];
    int lane = threadIdx.x & 31, wid = threadIdx.x >> 5, nw = (blockDim.x + 31) >> 5;
    v = warp_max(v);
    __syncthreads();
    if (lane == 0) sh[wid] = v;
    __syncthreads();
    if (wid == 0) {
        float x = (lane < nw) ? sh[lane] : -3.4e38f;
        x = warp_max(x);
        if (lane == 0) sh[0] = x;
    }
    __syncthreads();
    return sh[0];
}

// ---------------- weight conversion: fp32 [K][lds] -> interleaved half2 u32 [K/2][Nout]
__global__ void conv_w_kernel(const float* __restrict__ src, uint32_t* __restrict__ dst,
                              int K2, int Nout, int lds, int c0) {
    long i = (long)blockIdx.x * blockDim.x + threadIdx.x;
    long total = (long)K2 * (Nout >> 2);
    if (i >= total) return;
    int k2 = (int)(i / (Nout >> 2));
    int c  = (int)(i % (Nout >> 2)) << 2;
    float4 a = *(const float4*)(src + (long)(2 * k2) * lds + c0 + c);
    float4 b = *(const float4*)(src + (long)(2 * k2 + 1) * lds + c0 + c);
    uint4 o;
    o.x = pack_half2(a.x, b.x);
    o.y = pack_half2(a.y, b.y);
    o.z = pack_half2(a.z, b.z);
    o.w = pack_half2(a.w, b.w);
    *(uint4*)(dst + (long)k2 * Nout + c) = o;
}

// ---------------- elementwise / norm kernels ----------------
__global__ void rms_kernel(const float* __restrict__ in, const float* __restrict__ res,
                           const float* __restrict__ w, void* __restrict__ out,
                           int N, int outHalf) {
    int row = blockIdx.x;
    const float* x = in + (long)row * N;
    float sq = 0.f;
    for (int i = threadIdx.x; i < N; i += blockDim.x) { float v = x[i]; sq += v * v; }
    sq = block_sum(sq);
    float scale = rsqrtf(sq / (float)N + 1e-6f);
    const float* r = res ? res + (long)row * N : nullptr;
    if (outHalf) {
        __half* o = (__half*)out + (long)row * N;
        for (int i = threadIdx.x; i < N; i += blockDim.x)
            o[i] = __float2half_rn((r ? r[i] : 0.f) + x[i] * scale * w[i]);
    } else {
        float* o = (float*)out + (long)row * N;
        for (int i = threadIdx.x; i < N; i += blockDim.x)
            o[i] = (r ? r[i] : 0.f) + x[i] * scale * w[i];
    }
}

__global__ void ln_kernel(const __half* __restrict__ in, const float* __restrict__ s,
                          const float* __restrict__ b, __half* __restrict__ out,
                          int N, int ldin, int ldout) {
    int row = blockIdx.x;
    const __half* x = in + (long)row * ldin;
    float sum = 0.f, sq = 0.f;
    for (int i = threadIdx.x; i < N; i += blockDim.x) {
        float v = __half2float(x[i]);
        sum += v; sq += v * v;
    }
    sum = block_sum(sum);
    sq = block_sum(sq);
    float m = sum / (float)N;
    float var = sq / (float)N - m * m;
    float r = rsqrtf(var + 1e-6f);
    __half* o = out + (long)row * ldout;
    for (int i = threadIdx.x; i < N; i += blockDim.x)
        o[i] = __float2half_rn((__half2float(x[i]) - m) * r * s[i] + b[i]);
}

__global__ void rope_q_kernel(__half* __restrict__ q, const int* __restrict__ pos) {
    int srow = blockIdx.x;
    int t = threadIdx.x;         // 512 = 16 heads * 32 freq
    int h = t >> 5, j = t & 31;
    float p = (float)pos[srow];
    float invf = __expf(-((float)(2 * j)) / 64.f * 9.210340371976184f);
    float sn, c;
    sincosf(p * invf, &sn, &c);
    long base = (long)srow * HQH_ + h * QH_ + NOPE_;
    float x1 = __half2float(q[base + j]);
    float x2 = __half2float(q[base + 32 + j]);
    q[base + j]      = __float2half_rn(x1 * c - x2 * sn);
    q[base + 32 + j] = __float2half_rn(x2 * c + x1 * sn);
}

__global__ void build_kft_kernel(const __half* __restrict__ kv, const __half* __restrict__ ckv,
                                 const int* __restrict__ pos, uint32_t* __restrict__ kft2) {
    int srow = blockIdx.x;
    int k2 = threadIdx.x;        // 0..95
    uint32_t val;
    if (k2 < 64) {
        val = *(const uint32_t*)(kv + (long)srow * KVOUT_ + 2 * k2);
    } else {
        const __half* kp = ckv + (long)srow * CKV_ + KVL_;
        float p = (float)pos[srow];
        float v[2];
        #pragma unroll
        for (int u = 0; u < 2; u++) {
            int idx = 2 * k2 + u - 128;
            int jj = (idx < 32) ? idx : idx - 32;
            float invf = __expf(-((float)(2 * jj)) / 64.f * 9.210340371976184f);
            float sn, c;
            sincosf(p * invf, &sn, &c);
            float a = __half2float(kp[jj]);
            float b2 = __half2float(kp[jj + 32]);
            v[u] = (idx < 32) ? (a * c - b2 * sn) : (b2 * c + a * sn);
        }
        val = pack_half2(v[0], v[1]);
    }
    kft2[(long)k2 * S_ + srow] = val;
}

__global__ void build_v2_kernel(const __half* __restrict__ kv, uint32_t* __restrict__ v2) {
    int i = blockIdx.x * blockDim.x + threadIdx.x;
    if (i >= (S_ / 2) * VD_) return;
    int k2 = i >> 7, n = i & 127;
    float a = __half2float(kv[(long)(2 * k2) * KVOUT_ + NOPE_ + n]);
    float b = __half2float(kv[(long)(2 * k2 + 1) * KVOUT_ + NOPE_ + n]);
    v2[i] = pack_half2(a, b);
}

// causal softmax, 3-phase: max -> exp (stored fp32 in-place) -> scale to half P.
// Single __expf per lower-triangle element; zero-fill only the region the
// K-cut PV GEMM can read: (q, (q & ~127) + 192).
__global__ void softmax_kernel(float* __restrict__ scores, __half* __restrict__ P) {
    int q = blockIdx.x, h = blockIdx.y;
    float* row = scores + ((long)h * S_ + q) * S_;
    __half* prow = P + ((long)h * S_ + q) * S_;
    float mx = -3.4e38f;
    for (int k = threadIdx.x; k <= q; k += blockDim.x)
        mx = fmaxf(mx, row[k]);
    mx = block_max(mx);
    float sum = 0.f;
    for (int k = threadIdx.x; k <= q; k += blockDim.x) {
        float e = __expf(row[k] - mx);
        row[k] = e;                 // in-place fp32, no extra rounding
        sum += e;
    }
    sum = block_sum(sum);
    float inv = 1.f / sum;
    for (int k = threadIdx.x; k <= q; k += blockDim.x)
        prow[k] = __float2half_rn(row[k] * inv);
    int kend = min(S_, (q & ~127) + 192);
    for (int k = q + 1 + threadIdx.x; k < kend; k += blockDim.x)
        prow[k] = __float2half_rn(0.f);
}

__global__ void silu_mul_kernel(const __half* __restrict__ gu, __half* __restrict__ act) {
    long idx = (long)blockIdx.x * blockDim.x + threadIdx.x;
    int srow = (int)(idx >> 13);
    int i = (int)(idx & 8191);
    float g = __half2float(gu[(long)srow * (2 * INTER_) + i]);
    float u = __half2float(gu[(long)srow * (2 * INTER_) + INTER_ + i]);
    act[idx] = __float2half_rn(u * g / (1.f + __expf(-g)));
}

// ---------------- FP16 tensor-core GEMM (m16n8k16, fp32 accum) ----------------
__device__ __forceinline__ void cp_async16(uint32_t dst, const void* src, int szbytes) {
    asm volatile("cp.async.cg.shared.global [%0], [%1], 16, %2;\n"
                 :: "r"(dst), "l"(src), "r"(szbytes));
}

#define A_STRIDE_U32 20
#define B_STRIDE_U32 136
#define A_STAGE_B (128 * 80)
#define B_STAGE_B (16 * 544)
#define NSTAGE 3
#define GEMM_SMEM_BYTES (NSTAGE * (A_STAGE_B + B_STAGE_B))

__global__ __launch_bounds__(128) void h16gemm_kernel(
    const __half* __restrict__ A, const uint32_t* __restrict__ B2, void* __restrict__ Cv,
    int M, int N, int K, int lda, int ldb2, int ldc,
    long sA, long sB2, long sC, float alpha, int outHalf, int mode)
{
    const int bm = blockIdx.y * 128;
    const int bn = blockIdx.x * 128;
    if (mode == 1 && bn >= bm + 128) return;

    A  += (long)blockIdx.z * sA;
    B2 += (long)blockIdx.z * sB2;
    char* Cb = (char*)Cv + (long)blockIdx.z * sC * (outHalf ? 2 : 4);

    int ntiles = K >> 5;
    if (mode == 2) { int ke = (bm + 159) >> 5; if (ke < ntiles) ntiles = ke; }

    extern __shared__ __align__(16) char smem[];
    uint32_t smem_base = (uint32_t)__cvta_generic_to_shared(smem);
    const uint32_t a_base = smem_base;
    const uint32_t b_base = smem_base + NSTAGE * A_STAGE_B;

    const int t = threadIdx.x;
    const int warp = t >> 5;
    const int lane = t & 31;
    const int g  = lane >> 2;
    const int tg = lane & 3;
    const int wm = (warp & 1) * 64;
    const int wn = (warp >> 1) * 64;

    float acc[4][8][4];
    #pragma unroll
    for (int i = 0; i < 4; i++)
        #pragma unroll
        for (int j = 0; j < 8; j++)
            #pragma unroll
            for (int r = 0; r < 4; r++) acc[i][j][r] = 0.f;

    auto stage = [&](int kt) {
        int s = kt % NSTAGE;
        int k0 = kt << 5;
        uint32_t ao = a_base + (uint32_t)s * A_STAGE_B;
        #pragma unroll
        for (int it = 0; it < 4; it++) {
            int idx = t + 128 * it;
            int row = idx >> 2;
            int c   = idx & 3;
            cp_async16(ao + (uint32_t)(row * 80 + c * 16),
                       A + (long)(bm + row) * lda + k0 + c * 8, 16);
        }
        uint32_t bo = b_base + (uint32_t)s * B_STAGE_B;
        int k20 = kt << 4;
        #pragma unroll
        for (int it = 0; it < 4; it++) {
            int idx = t + 128 * it;
            int row = idx >> 5;
            int c4  = (idx & 31) * 4;
            int col = bn + c4;
            int sz = (col < N) ? 16 : 0;
            cp_async16(bo + (uint32_t)(row * 544 + c4 * 4),
                       B2 + (long)(k20 + row) * ldb2 + col, sz);
        }
    };

    stage(0);
    asm volatile("cp.async.commit_group;\n");
    stage(1);
    asm volatile("cp.async.commit_group;\n");

    for (int kt = 0; kt < ntiles; kt++) {
        asm volatile("cp.async.wait_group 1;\n");
        __syncthreads();

        const uint32_t* As = (const uint32_t*)(smem + (kt % NSTAGE) * A_STAGE_B);
        const uint32_t* Bs = (const uint32_t*)(smem + NSTAGE * A_STAGE_B + (kt % NSTAGE) * B_STAGE_B);

        #pragma unroll
        for (int kk2 = 0; kk2 < 16; kk2 += 8) {
            uint32_t af[4][4];
            #pragma unroll
            for (int i = 0; i < 4; i++) {
                int r0 = wm + 16 * i + g;
                af[i][0] = As[(r0)     * A_STRIDE_U32 + kk2 + tg];
                af[i][1] = As[(r0 + 8) * A_STRIDE_U32 + kk2 + tg];
                af[i][2] = As[(r0)     * A_STRIDE_U32 + kk2 + tg + 4];
                af[i][3] = As[(r0 + 8) * A_STRIDE_U32 + kk2 + tg + 4];
            }
            uint32_t bf[8][2];
            #pragma unroll
            for (int j = 0; j < 8; j++) {
                int c0 = wn + 8 * j + g;
                bf[j][0] = Bs[(kk2 + tg)     * B_STRIDE_U32 + c0];
                bf[j][1] = Bs[(kk2 + tg + 4) * B_STRIDE_U32 + c0];
            }
            #pragma unroll
            for (int i = 0; i < 4; i++)
                #pragma unroll
                for (int j = 0; j < 8; j++) {
                    asm volatile(
                        "mma.sync.aligned.m16n8k16.row.col.f32.f16.f16.f32 "
                        "{%0,%1,%2,%3}, {%4,%5,%6,%7}, {%8,%9}, {%0,%1,%2,%3};\n"
                        : "+f"(acc[i][j][0]), "+f"(acc[i][j][1]),
                          "+f"(acc[i][j][2]), "+f"(acc[i][j][3])
                        : "r"(af[i][0]), "r"(af[i][1]), "r"(af[i][2]), "r"(af[i][3]),
                          "r"(bf[j][0]), "r"(bf[j][1]));
                }
        }
        __syncthreads();
        if (kt + 2 < ntiles) stage(kt + 2);
        asm volatile("cp.async.commit_group;\n");
    }

    if (outHalf) {
        __half* C = (__half*)Cb;
        #pragma unroll
        for (int i = 0; i < 4; i++)
            #pragma unroll
            for (int j = 0; j < 8; j++) {
                int r0 = bm + wm + 16 * i + g;
                int c0 = bn + wn + 8 * j + 2 * tg;
                if (c0 < N) {
                    *(uint32_t*)(C + (long)r0 * ldc + c0) =
                        pack_half2(acc[i][j][0] * alpha, acc[i][j][1] * alpha);
                    *(uint32_t*)(C + (long)(r0 + 8) * ldc + c0) =
                        pack_half2(acc[i][j][2] * alpha, acc[i][j][3] * alpha);
                }
            }
    } else {
        float* C = (float*)Cb;
        #pragma unroll
        for (int i = 0; i < 4; i++)
            #pragma unroll
            for (int j = 0; j < 8; j++) {
                int r0 = bm + wm + 16 * i + g;
                int c0 = bn + wn + 8 * j + 2 * tg;
                if (c0 < N) {
                    *(float2*)(C + (long)r0 * ldc + c0) =
                        make_float2(acc[i][j][0] * alpha, acc[i][j][1] * alpha);
                    *(float2*)(C + (long)(r0 + 8) * ldc + c0) =
                        make_float2(acc[i][j][2] * alpha, acc[i][j][3] * alpha);
                }
            }
    }
}

static inline void launch_gemm(const __half* A, const uint32_t* B2, void* C,
                               int M, int N, int K, int lda, int ldb2, int ldc,
                               long sA, long sB2, long sC, float alpha, int batch,
                               int outHalf, int mode) {
    static bool attr_set = false;
    if (!attr_set) {
        cudaFuncSetAttribute(h16gemm_kernel,
                             cudaFuncAttributeMaxDynamicSharedMemorySize, GEMM_SMEM_BYTES);
        attr_set = true;
    }
    dim3 grid((N + 127) / 128, M / 128, batch);
    h16gemm_kernel<<<grid, 128, GEMM_SMEM_BYTES>>>(A, B2, C, M, N, K, lda, ldb2, ldc,
                                                   sA, sB2, sC, alpha, outHalf, mode);
}

// ---------------- entry ----------------
extern "C" void kernel_launch(void* const* d_in, const int* in_sizes, int n_in,
                              void* d_out, int out_size) {
    const float* hidden      = (const float*)d_in[0];
    // d_in[1] attention_mask: all-ones; unused (pure causal).
    const int*   pos         = (const int*)d_in[2];
    const float* w_in        = (const float*)d_in[3];
    const float* w_post_attn = (const float*)d_in[4];
    const float* w_pre_ff    = (const float*)d_in[5];
    const float* w_post_ff   = (const float*)d_in[6];
    const float* qa_w        = (const float*)d_in[7];
    const float* qa_ln_s     = (const float*)d_in[8];
    const float* qa_ln_b     = (const float*)d_in[9];
    const float* qb_w        = (const float*)d_in[10];
    const float* kv_mqa_w    = (const float*)d_in[11];
    const float* kv_ln_s     = (const float*)d_in[12];
    const float* kv_ln_b     = (const float*)d_in[13];
    const float* kvi_w       = (const float*)d_in[14];
    const float* o_w         = (const float*)d_in[15];
    const float* gate_up_w   = (const float*)d_in[16];
    const float* down_w      = (const float*)d_in[17];
    float* out = (float*)d_out;

    unsigned char* sc = nullptr;
    cudaGetSymbolAddress((void**)&sc, g_scratch);
    float*    scoresF = (float*)(sc + OB_SCORES);
    __half*   Ph      = (__half*)(sc + OB_P);
    __half*   h1h     = (__half*)(sc + OB_H1);
    __half*   qah     = (__half*)(sc + OB_QA);
    __half*   qh      = (__half*)(sc + OB_Q);
    __half*   ckvh    = (__half*)(sc + OB_CKV);
    __half*   kvlnh   = (__half*)(sc + OB_KVLN);
    __half*   kvh     = (__half*)(sc + OB_KV);
    uint32_t* kft2    = (uint32_t*)(sc + OB_KFT);
    uint32_t* v2      = (uint32_t*)(sc + OB_V2);
    __half*   attnoh  = (__half*)(sc + OB_ATTNO);
    float*    attnprojF = (float*)(sc + OB_ATTNPROJ);
    float*    xF      = (float*)(sc + OB_X);
    __half*   h2h     = (__half*)(sc + OB_H2);
    __half*   guh     = (__half*)(sc + OB_GU);
    __half*   acth    = (__half*)(sc + OB_ACT);
    float*    mlpF    = (float*)(sc + OB_MLP);
    uint32_t* Wqa = (uint32_t*)(sc + OB_WQA);
    uint32_t* Wqb = (uint32_t*)(sc + OB_WQB);
    uint32_t* Wkv = (uint32_t*)(sc + OB_WKV);
    uint32_t* Wkvi = (uint32_t*)(sc + OB_WKVI);
    uint32_t* Wo  = (uint32_t*)(sc + OB_WO);
    uint32_t* Wgu = (uint32_t*)(sc + OB_WGU);
    uint32_t* Wdn = (uint32_t*)(sc + OB_WDN);

    auto cw = [&](const float* s, uint32_t* d, int K, int Nout, int lds, int c0) {
        long total = (long)(K / 2) * (Nout / 4);
        conv_w_kernel<<<(int)((total + 255) / 256), 256>>>(s, d, K / 2, Nout, lds, c0);
    };
    cw(qa_w,      Wqa,  HID_, QL_,        QL_,              0);
    cw(qb_w,      Wqb,  QL_,  HQH_,       HQH_,             0);
    cw(kv_mqa_w,  Wkv,  HID_, CKV_,       CKV_,             0);
    cw(kvi_w,     Wkvi, KVL_, KVOUT_,     H_ * (NOPE_+VD_), 0);
    cw(o_w,       Wo,   HID_, HID_,       HID_,             0);
    cw(gate_up_w, Wgu,  HID_, 2 * INTER_, 2 * INTER_,       0);
    cw(down_w,    Wdn,  INTER_, HID_,     HID_,             0);

    rms_kernel<<<S_, 256>>>(hidden, nullptr, w_in, h1h, HID_, 1);

    launch_gemm(h1h, Wqa, qah, S_, QL_, HID_, HID_, QL_, QL_, 0, 0, 0, 1.f, 1, 1, 0);
    ln_kernel<<<S_, 256>>>(qah, qa_ln_s, qa_ln_b, qah, QL_, QL_, QL_);

    launch_gemm(qah, Wqb, qh, S_, HQH_, QL_, QL_, HQH_, HQH_, 0, 0, 0, 1.f, 1, 1, 0);

    launch_gemm(h1h, Wkv, ckvh, S_, CKV_, HID_, HID_, CKV_, CKV_, 0, 0, 0, 1.f, 1, 1, 0);
    ln_kernel<<<S_, 256>>>(ckvh, kv_ln_s, kv_ln_b, kvlnh, KVL_, CKV_, KVL_);

    launch_gemm(kvlnh, Wkvi, kvh, S_, KVOUT_, KVL_, KVL_, KVOUT_, KVOUT_, 0, 0, 0, 1.f, 1, 1, 0);

    rope_q_kernel<<<S_, 512>>>(qh, pos);
    build_kft_kernel<<<S_, 96>>>(kvh, ckvh, pos, kft2);
    build_v2_kernel<<<(S_ / 2 * VD_ + 255) / 256, 256>>>(kvh, v2);

    const float scale = 0.07216878364870323f;   // 192^-0.5
    launch_gemm(qh, kft2, scoresF, S_, S_, KFD_, HQH_, S_, S_,
                (long)QH_, 0L, (long)S_ * S_, scale, H_, 0, 1);

    softmax_kernel<<<dim3(S_, H_), 256>>>(scoresF, Ph);

    launch_gemm(Ph, v2, attnoh, S_, VD_, S_, S_, VD_, HID_,
                (long)S_ * S_, 0L, (long)VD_, 1.f, H_, 1, 2);

    launch_gemm(attnoh, Wo, attnprojF, S_, HID_, HID_, HID_, HID_, HID_, 0, 0, 0, 1.f, 1, 0, 0);

    rms_kernel<<<S_, 256>>>(attnprojF, hidden, w_post_attn, xF, HID_, 0);
    rms_kernel<<<S_, 256>>>(xF, nullptr, w_pre_ff, h2h, HID_, 1);

    launch_gemm(h2h, Wgu, guh, S_, 2 * INTER_, HID_, HID_, 2 * INTER_, 2 * INTER_, 0, 0, 0, 1.f, 1, 1, 0);
    silu_mul_kernel<<<(S_ * INTER_) / 256, 256>>>(guh, acth);

    launch_gemm(acth, Wdn, mlpF, S_, HID_, INTER_, INTER_, HID_, HID_, 0, 0, 0, 1.f, 1, 0, 0);

    rms_kernel<<<S_, 256>>>(mlpF, xF, w_post_ff, out, HID_, 0);
}

// round 11
// speedup vs baseline: 1.8942x; 1.0757x over previous
#include <cuda_runtime.h>
#include <cuda_fp16.h>
#include <math.h>
#include <stdint.h>

// ---------------- problem constants ----------------
#define S_   2048
#define HID_ 2048
#define H_   16
#define NOPE_ 128
#define ROPE_ 64
#define VD_  128
#define QH_  192
#define QL_  1536
#define KVL_ 512
#define CKV_ 576
#define INTER_ 8192
#define HQH_ 3072
#define KVOUT_ 256
#define KFD_ 192

// ---------------- scratch byte offsets ----------------
#define OB_SCORES   0L
#define OB_P        268435456L
#define OB_H1       402653184L
#define OB_QA       411041792L
#define OB_Q        417333248L
#define OB_CKV      429916160L
#define OB_KVLN     432275456L
#define OB_KV       434372608L
#define OB_KFT      435421184L
#define OB_V2       436207616L
#define OB_ATTNO    436731904L
#define OB_ATTNPROJ 445120512L
#define OB_X        461897728L
#define OB_H2       478674944L
#define OB_GU       487063552L
#define OB_ACT      554172416L
#define OB_MLP      587726848L
#define OB_WQA      604504064L
#define OB_WQB      610795520L
#define OB_WKV      620232704L
#define OB_WKVI     622592000L
#define OB_WO       622854144L
#define OB_WGU      631242752L
#define OB_WDN      698351616L
#define SCRATCH_BYTES 732000000L

__device__ __align__(256) unsigned char g_scratch[SCRATCH_BYTES];

__device__ __forceinline__ uint32_t pack_half2(float a, float b) {
    __half2 h = __floats2half2_rn(a, b);
    return *(uint32_t*)&h;
}

// ---------------- reductions ----------------
__device__ __forceinline__ float warp_sum(float v) {
    #pragma unroll
    for (int o = 16; o > 0; o >>= 1) v += __shfl_xor_sync(0xffffffffu, v, o);
    return v;
}
__device__ __forceinline__ float warp_max(float v) {
    #pragma unroll
    for (int o = 16; o > 0; o >>= 1) v = fmaxf(v, __shfl_xor_sync(0xffffffffu, v, o));
    return v;
}
__device__ float block_sum(float v) {
    __shared__ float sh[32];
    int lane = threadIdx.x & 31, wid = threadIdx.x >> 5, nw = (blockDim.x + 31) >> 5;
    v = warp_sum(v);
    __syncthreads();
    if (lane == 0) sh[wid] = v;
    __syncthreads();
    if (wid == 0) {
        float x = (lane < nw) ? sh[lane] : 0.f;
        x = warp_sum(x);
        if (lane == 0) sh[0] = x;
    }
    __syncthreads();
    return sh[0];
}
__device__ float block_max(float v) {
    __shared__ float sh[32];
    int lane = threadIdx.x & 31, wid = threadIdx.x >> 5, nw = (blockDim.x + 31) >> 5;
    v = warp_max(v);
    __syncthreads();
    if (lane == 0) sh[wid] = v;
    __syncthreads();
    if (wid == 0) {
        float x = (lane < nw) ? sh[lane] : -3.4e38f;
        x = warp_max(x);
        if (lane == 0) sh[0] = x;
    }
    __syncthreads();
    return sh[0];
}

// ---------------- weight conversion: fp32 [K][lds] -> interleaved half2 u32 [K/2][Nout]
__global__ void conv_w_kernel(const float* __restrict__ src, uint32_t* __restrict__ dst,
                              int K2, int Nout, int lds, int c0) {
    long i = (long)blockIdx.x * blockDim.x + threadIdx.x;
    long total = (long)K2 * (Nout >> 2);
    if (i >= total) return;
    int k2 = (int)(i / (Nout >> 2));
    int c  = (int)(i % (Nout >> 2)) << 2;
    float4 a = *(const float4*)(src + (long)(2 * k2) * lds + c0 + c);
    float4 b = *(const float4*)(src + (long)(2 * k2 + 1) * lds + c0 + c);
    uint4 o;
    o.x = pack_half2(a.x, b.x);
    o.y = pack_half2(a.y, b.y);
    o.z = pack_half2(a.z, b.z);
    o.w = pack_half2(a.w, b.w);
    *(uint4*)(dst + (long)k2 * Nout + c) = o;
}

// ---------------- elementwise / norm kernels ----------------
__global__ void rms_kernel(const float* __restrict__ in, const float* __restrict__ res,
                           const float* __restrict__ w, void* __restrict__ out,
                           int N, int outHalf) {
    int row = blockIdx.x;
    const float* x = in + (long)row * N;
    float sq = 0.f;
    for (int i = threadIdx.x; i < N; i += blockDim.x) { float v = x[i]; sq += v * v; }
    sq = block_sum(sq);
    float scale = rsqrtf(sq / (float)N + 1e-6f);
    const float* r = res ? res + (long)row * N : nullptr;
    if (outHalf) {
        __half* o = (__half*)out + (long)row * N;
        for (int i = threadIdx.x; i < N; i += blockDim.x)
            o[i] = __float2half_rn((r ? r[i] : 0.f) + x[i] * scale * w[i]);
    } else {
        float* o = (float*)out + (long)row * N;
        for (int i = threadIdx.x; i < N; i += blockDim.x)
            o[i] = (r ? r[i] : 0.f) + x[i] * scale * w[i];
    }
}

__global__ void ln_kernel(const __half* __restrict__ in, const float* __restrict__ s,
                          const float* __restrict__ b, __half* __restrict__ out,
                          int N, int ldin, int ldout) {
    int row = blockIdx.x;
    const __half* x = in + (long)row * ldin;
    float sum = 0.f, sq = 0.f;
    for (int i = threadIdx.x; i < N; i += blockDim.x) {
        float v = __half2float(x[i]);
        sum += v; sq += v * v;
    }
    sum = block_sum(sum);
    sq = block_sum(sq);
    float m = sum / (float)N;
    float var = sq / (float)N - m * m;
    float r = rsqrtf(var + 1e-6f);
    __half* o = out + (long)row * ldout;
    for (int i = threadIdx.x; i < N; i += blockDim.x)
        o[i] = __float2half_rn((__half2float(x[i]) - m) * r * s[i] + b[i]);
}

__global__ void rope_q_kernel(__half* __restrict__ q, const int* __restrict__ pos) {
    int srow = blockIdx.x;
    int t = threadIdx.x;
    int h = t >> 5, j = t & 31;
    float p = (float)pos[srow];
    float invf = __expf(-((float)(2 * j)) / 64.f * 9.210340371976184f);
    float sn, c;
    sincosf(p * invf, &sn, &c);
    long base = (long)srow * HQH_ + h * QH_ + NOPE_;
    float x1 = __half2float(q[base + j]);
    float x2 = __half2float(q[base + 32 + j]);
    q[base + j]      = __float2half_rn(x1 * c - x2 * sn);
    q[base + 32 + j] = __float2half_rn(x2 * c + x1 * sn);
}

__global__ void build_kft_kernel(const __half* __restrict__ kv, const __half* __restrict__ ckv,
                                 const int* __restrict__ pos, uint32_t* __restrict__ kft2) {
    int srow = blockIdx.x;
    int k2 = threadIdx.x;        // 0..95
    uint32_t val;
    if (k2 < 64) {
        val = *(const uint32_t*)(kv + (long)srow * KVOUT_ + 2 * k2);
    } else {
        const __half* kp = ckv + (long)srow * CKV_ + KVL_;
        float p = (float)pos[srow];
        float v[2];
        #pragma unroll
        for (int u = 0; u < 2; u++) {
            int idx = 2 * k2 + u - 128;
            int jj = (idx < 32) ? idx : idx - 32;
            float invf = __expf(-((float)(2 * jj)) / 64.f * 9.210340371976184f);
            float sn, c;
            sincosf(p * invf, &sn, &c);
            float a = __half2float(kp[jj]);
            float b2 = __half2float(kp[jj + 32]);
            v[u] = (idx < 32) ? (a * c - b2 * sn) : (b2 * c + a * sn);
        }
        val = pack_half2(v[0], v[1]);
    }
    kft2[(long)k2 * S_ + srow] = val;
}

__global__ void build_v2_kernel(const __half* __restrict__ kv, uint32_t* __restrict__ v2) {
    int i = blockIdx.x * blockDim.x + threadIdx.x;
    if (i >= (S_ / 2) * VD_) return;
    int k2 = i >> 7, n = i & 127;
    float a = __half2float(kv[(long)(2 * k2) * KVOUT_ + NOPE_ + n]);
    float b = __half2float(kv[(long)(2 * k2 + 1) * KVOUT_ + NOPE_ + n]);
    v2[i] = pack_half2(a, b);
}

// causal softmax, in-place exp, fill only PV-visible zero region
__global__ void softmax_kernel(float* __restrict__ scores, __half* __restrict__ P) {
    int q = blockIdx.x, h = blockIdx.y;
    float* row = scores + ((long)h * S_ + q) * S_;
    __half* prow = P + ((long)h * S_ + q) * S_;
    float mx = -3.4e38f;
    for (int k = threadIdx.x; k <= q; k += blockDim.x)
        mx = fmaxf(mx, row[k]);
    mx = block_max(mx);
    float sum = 0.f;
    for (int k = threadIdx.x; k <= q; k += blockDim.x) {
        float e = __expf(row[k] - mx);
        row[k] = e;
        sum += e;
    }
    sum = block_sum(sum);
    float inv = 1.f / sum;
    for (int k = threadIdx.x; k <= q; k += blockDim.x)
        prow[k] = __float2half_rn(row[k] * inv);
    int kend = min(S_, (q & ~127) + 192);
    for (int k = q + 1 + threadIdx.x; k < kend; k += blockDim.x)
        prow[k] = __float2half_rn(0.f);
}

__global__ void silu_mul_kernel(const __half* __restrict__ gu, __half* __restrict__ act) {
    long idx = (long)blockIdx.x * blockDim.x + threadIdx.x;
    int srow = (int)(idx >> 13);
    int i = (int)(idx & 8191);
    float g = __half2float(gu[(long)srow * (2 * INTER_) + i]);
    float u = __half2float(gu[(long)srow * (2 * INTER_) + INTER_ + i]);
    act[idx] = __float2half_rn(u * g / (1.f + __expf(-g)));
}

// ---------------- FP16 tensor-core GEMM (m16n8k16, fp32 accum) ----------------
__device__ __forceinline__ void cp_async16(uint32_t dst, const void* src, int szbytes) {
    asm volatile("cp.async.cg.shared.global [%0], [%1], 16, %2;\n"
                 :: "r"(dst), "l"(src), "r"(szbytes));
}

#define A_STRIDE_U32 20
#define B_STRIDE_U32 136
#define A_STAGE_B (128 * 80)
#define B_STAGE_B (16 * 544)
#define NSTAGE 3
#define GEMM_SMEM_BYTES (NSTAGE * (A_STAGE_B + B_STAGE_B))

__global__ __launch_bounds__(128) void h16gemm_kernel(
    const __half* __restrict__ A, const uint32_t* __restrict__ B2, void* __restrict__ Cv,
    int M, int N, int K, int lda, int ldb2, int ldc,
    long sA, long sB2, long sC, float alpha, int outHalf, int mode)
{
    const int bm = blockIdx.y * 128;
    const int bn = blockIdx.x * 128;
    if (mode == 1 && bn >= bm + 128) return;

    A  += (long)blockIdx.z * sA;
    B2 += (long)blockIdx.z * sB2;
    char* Cb = (char*)Cv + (long)blockIdx.z * sC * (outHalf ? 2 : 4);

    int ntiles = K >> 5;
    if (mode == 2) { int ke = (bm + 159) >> 5; if (ke < ntiles) ntiles = ke; }

    extern __shared__ __align__(16) char smem[];
    uint32_t smem_base = (uint32_t)__cvta_generic_to_shared(smem);
    const uint32_t a_base = smem_base;
    const uint32_t b_base = smem_base + NSTAGE * A_STAGE_B;

    const int t = threadIdx.x;
    const int warp = t >> 5;
    const int lane = t & 31;
    const int g  = lane >> 2;
    const int tg = lane & 3;
    const int wm = (warp & 1) * 64;
    const int wn = (warp >> 1) * 64;

    float acc[4][8][4];
    #pragma unroll
    for (int i = 0; i < 4; i++)
        #pragma unroll
        for (int j = 0; j < 8; j++)
            #pragma unroll
            for (int r = 0; r < 4; r++) acc[i][j][r] = 0.f;

    auto stage = [&](int kt) {
        int s = kt % NSTAGE;
        int k0 = kt << 5;
        uint32_t ao = a_base + (uint32_t)s * A_STAGE_B;
        #pragma unroll
        for (int it = 0; it < 4; it++) {
            int idx = t + 128 * it;
            int row = idx >> 2;
            int c   = idx & 3;
            cp_async16(ao + (uint32_t)(row * 80 + c * 16),
                       A + (long)(bm + row) * lda + k0 + c * 8, 16);
        }
        uint32_t bo = b_base + (uint32_t)s * B_STAGE_B;
        int k20 = kt << 4;
        #pragma unroll
        for (int it = 0; it < 4; it++) {
            int idx = t + 128 * it;
            int row = idx >> 5;
            int c4  = (idx & 31) * 4;
            int col = bn + c4;
            int sz = (col < N) ? 16 : 0;
            cp_async16(bo + (uint32_t)(row * 544 + c4 * 4),
                       B2 + (long)(k20 + row) * ldb2 + col, sz);
        }
    };

    stage(0);
    asm volatile("cp.async.commit_group;\n");
    stage(1);
    asm volatile("cp.async.commit_group;\n");

    for (int kt = 0; kt < ntiles; kt++) {
        asm volatile("cp.async.wait_group 1;\n");
        __syncthreads();

        const uint32_t* As = (const uint32_t*)(smem + (kt % NSTAGE) * A_STAGE_B);
        const uint32_t* Bs = (const uint32_t*)(smem + NSTAGE * A_STAGE_B + (kt % NSTAGE) * B_STAGE_B);

        #pragma unroll
        for (int kk2 = 0; kk2 < 16; kk2 += 8) {
            uint32_t af[4][4];
            #pragma unroll
            for (int i = 0; i < 4; i++) {
                int r0 = wm + 16 * i + g;
                af[i][0] = As[(r0)     * A_STRIDE_U32 + kk2 + tg];
                af[i][1] = As[(r0 + 8) * A_STRIDE_U32 + kk2 + tg];
                af[i][2] = As[(r0)     * A_STRIDE_U32 + kk2 + tg + 4];
                af[i][3] = As[(r0 + 8) * A_STRIDE_U32 + kk2 + tg + 4];
            }
            uint32_t bf[8][2];
            #pragma unroll
            for (int j = 0; j < 8; j++) {
                int c0 = wn + 8 * j + g;
                bf[j][0] = Bs[(kk2 + tg)     * B_STRIDE_U32 + c0];
                bf[j][1] = Bs[(kk2 + tg + 4) * B_STRIDE_U32 + c0];
            }
            #pragma unroll
            for (int i = 0; i < 4; i++)
                #pragma unroll
                for (int j = 0; j < 8; j++) {
                    asm volatile(
                        "mma.sync.aligned.m16n8k16.row.col.f32.f16.f16.f32 "
                        "{%0,%1,%2,%3}, {%4,%5,%6,%7}, {%8,%9}, {%0,%1,%2,%3};\n"
                        : "+f"(acc[i][j][0]), "+f"(acc[i][j][1]),
                          "+f"(acc[i][j][2]), "+f"(acc[i][j][3])
                        : "r"(af[i][0]), "r"(af[i][1]), "r"(af[i][2]), "r"(af[i][3]),
                          "r"(bf[j][0]), "r"(bf[j][1]));
                }
        }
        __syncthreads();
        if (kt + 2 < ntiles) stage(kt + 2);
        asm volatile("cp.async.commit_group;\n");
    }

    if (outHalf) {
        __half* C = (__half*)Cb;
        #pragma unroll
        for (int i = 0; i < 4; i++)
            #pragma unroll
            for (int j = 0; j < 8; j++) {
                int r0 = bm + wm + 16 * i + g;
                int c0 = bn + wn + 8 * j + 2 * tg;
                if (c0 < N) {
                    *(uint32_t*)(C + (long)r0 * ldc + c0) =
                        pack_half2(acc[i][j][0] * alpha, acc[i][j][1] * alpha);
                    *(uint32_t*)(C + (long)(r0 + 8) * ldc + c0) =
                        pack_half2(acc[i][j][2] * alpha, acc[i][j][3] * alpha);
                }
            }
    } else {
        float* C = (float*)Cb;
        #pragma unroll
        for (int i = 0; i < 4; i++)
            #pragma unroll
            for (int j = 0; j < 8; j++) {
                int r0 = bm + wm + 16 * i + g;
                int c0 = bn + wn + 8 * j + 2 * tg;
                if (c0 < N) {
                    *(float2*)(C + (long)r0 * ldc + c0) =
                        make_float2(acc[i][j][0] * alpha, acc[i][j][1] * alpha);
                    *(float2*)(C + (long)(r0 + 8) * ldc + c0) =
                        make_float2(acc[i][j][2] * alpha, acc[i][j][3] * alpha);
                }
            }
    }
}

static inline void launch_gemm_s(cudaStream_t st, const __half* A, const uint32_t* B2, void* C,
                                 int M, int N, int K, int lda, int ldb2, int ldc,
                                 long sA, long sB2, long sC, float alpha, int batch,
                                 int outHalf, int mode) {
    dim3 grid((N + 127) / 128, M / 128, batch);
    h16gemm_kernel<<<grid, 128, GEMM_SMEM_BYTES, st>>>(A, B2, C, M, N, K, lda, ldb2, ldc,
                                                       sA, sB2, sC, alpha, outHalf, mode);
}

// ---------------- entry ----------------
extern "C" void kernel_launch(void* const* d_in, const int* in_sizes, int n_in,
                              void* d_out, int out_size) {
    const float* hidden      = (const float*)d_in[0];
    // d_in[1] attention_mask: all-ones; unused (pure causal).
    const int*   pos         = (const int*)d_in[2];
    const float* w_in        = (const float*)d_in[3];
    const float* w_post_attn = (const float*)d_in[4];
    const float* w_pre_ff    = (const float*)d_in[5];
    const float* w_post_ff   = (const float*)d_in[6];
    const float* qa_w        = (const float*)d_in[7];
    const float* qa_ln_s     = (const float*)d_in[8];
    const float* qa_ln_b     = (const float*)d_in[9];
    const float* qb_w        = (const float*)d_in[10];
    const float* kv_mqa_w    = (const float*)d_in[11];
    const float* kv_ln_s     = (const float*)d_in[12];
    const float* kv_ln_b     = (const float*)d_in[13];
    const float* kvi_w       = (const float*)d_in[14];
    const float* o_w         = (const float*)d_in[15];
    const float* gate_up_w   = (const float*)d_in[16];
    const float* down_w      = (const float*)d_in[17];
    float* out = (float*)d_out;

    unsigned char* sc = nullptr;
    cudaGetSymbolAddress((void**)&sc, g_scratch);
    float*    scoresF = (float*)(sc + OB_SCORES);
    __half*   Ph      = (__half*)(sc + OB_P);
    __half*   h1h     = (__half*)(sc + OB_H1);
    __half*   qah     = (__half*)(sc + OB_QA);
    __half*   qh      = (__half*)(sc + OB_Q);
    __half*   ckvh    = (__half*)(sc + OB_CKV);
    __half*   kvlnh   = (__half*)(sc + OB_KVLN);
    __half*   kvh     = (__half*)(sc + OB_KV);
    uint32_t* kft2    = (uint32_t*)(sc + OB_KFT);
    uint32_t* v2      = (uint32_t*)(sc + OB_V2);
    __half*   attnoh  = (__half*)(sc + OB_ATTNO);
    float*    attnprojF = (float*)(sc + OB_ATTNPROJ);
    float*    xF      = (float*)(sc + OB_X);
    __half*   h2h     = (__half*)(sc + OB_H2);
    __half*   guh     = (__half*)(sc + OB_GU);
    __half*   acth    = (__half*)(sc + OB_ACT);
    float*    mlpF    = (float*)(sc + OB_MLP);
    uint32_t* Wqa = (uint32_t*)(sc + OB_WQA);
    uint32_t* Wqb = (uint32_t*)(sc + OB_WQB);
    uint32_t* Wkv = (uint32_t*)(sc + OB_WKV);
    uint32_t* Wkvi = (uint32_t*)(sc + OB_WKVI);
    uint32_t* Wo  = (uint32_t*)(sc + OB_WO);
    uint32_t* Wgu = (uint32_t*)(sc + OB_WGU);
    uint32_t* Wdn = (uint32_t*)(sc + OB_WDN);

    // ---- one-time setup of streams/events (no device memory) ----
    static cudaStream_t s2 = nullptr, s3 = nullptr;
    static cudaEvent_t evFork, evFork2, evWsmall, evWbig, evKv;
    static bool init_done = false;
    if (!init_done) {
        cudaStreamCreateWithFlags(&s2, cudaStreamNonBlocking);
        cudaStreamCreateWithFlags(&s3, cudaStreamNonBlocking);
        cudaEventCreateWithFlags(&evFork,   cudaEventDisableTiming);
        cudaEventCreateWithFlags(&evFork2,  cudaEventDisableTiming);
        cudaEventCreateWithFlags(&evWsmall, cudaEventDisableTiming);
        cudaEventCreateWithFlags(&evWbig,   cudaEventDisableTiming);
        cudaEventCreateWithFlags(&evKv,     cudaEventDisableTiming);
        cudaFuncSetAttribute(h16gemm_kernel,
                             cudaFuncAttributeMaxDynamicSharedMemorySize, GEMM_SMEM_BYTES);
        init_done = true;
    }
    cudaStream_t s0 = 0;   // origin (capture) stream

    auto cw = [&](cudaStream_t st, const float* s, uint32_t* d, int K, int Nout, int lds) {
        long total = (long)(K / 2) * (Nout / 4);
        conv_w_kernel<<<(int)((total + 255) / 256), 256, 0, st>>>(s, d, K / 2, Nout, lds, 0);
    };

    // ---- fork s2: weight conversions ----
    cudaEventRecord(evFork, s0);
    cudaStreamWaitEvent(s2, evFork, 0);
    cw(s2, qa_w,      Wqa,  HID_, QL_,        QL_);
    cw(s2, qb_w,      Wqb,  QL_,  HQH_,       HQH_);
    cw(s2, kv_mqa_w,  Wkv,  HID_, CKV_,       CKV_);
    cw(s2, kvi_w,     Wkvi, KVL_, KVOUT_,     H_ * (NOPE_ + VD_));
    cudaEventRecord(evWsmall, s2);
    cw(s2, o_w,       Wo,   HID_, HID_,       HID_);
    cw(s2, gate_up_w, Wgu,  HID_, 2 * INTER_, 2 * INTER_);
    cw(s2, down_w,    Wdn,  INTER_, HID_,     HID_);
    cudaEventRecord(evWbig, s2);

    // ---- origin: h1 = rms(hidden)*w_in ----
    rms_kernel<<<S_, 256, 0, s0>>>(hidden, nullptr, w_in, h1h, HID_, 1);
    cudaEventRecord(evFork2, s0);

    // ---- fork s3: kv chain (needs h1 + small weights) ----
    cudaStreamWaitEvent(s3, evFork2, 0);
    cudaStreamWaitEvent(s3, evWsmall, 0);
    launch_gemm_s(s3, h1h, Wkv, ckvh, S_, CKV_, HID_, HID_, CKV_, CKV_, 0, 0, 0, 1.f, 1, 1, 0);
    ln_kernel<<<S_, 256, 0, s3>>>(ckvh, kv_ln_s, kv_ln_b, kvlnh, KVL_, CKV_, KVL_);
    launch_gemm_s(s3, kvlnh, Wkvi, kvh, S_, KVOUT_, KVL_, KVL_, KVOUT_, KVOUT_, 0, 0, 0, 1.f, 1, 1, 0);
    build_kft_kernel<<<S_, 96, 0, s3>>>(kvh, ckvh, pos, kft2);
    build_v2_kernel<<<(S_ / 2 * VD_ + 255) / 256, 256, 0, s3>>>(kvh, v2);
    cudaEventRecord(evKv, s3);

    // ---- origin: q chain (needs small weights) ----
    cudaStreamWaitEvent(s0, evWsmall, 0);
    launch_gemm_s(s0, h1h, Wqa, qah, S_, QL_, HID_, HID_, QL_, QL_, 0, 0, 0, 1.f, 1, 1, 0);
    ln_kernel<<<S_, 256, 0, s0>>>(qah, qa_ln_s, qa_ln_b, qah, QL_, QL_, QL_);
    launch_gemm_s(s0, qah, Wqb, qh, S_, HQH_, QL_, QL_, HQH_, HQH_, 0, 0, 0, 1.f, 1, 1, 0);
    rope_q_kernel<<<S_, 512, 0, s0>>>(qh, pos);

    // ---- join kv chain; attention ----
    cudaStreamWaitEvent(s0, evKv, 0);
    const float scale = 0.07216878364870323f;   // 192^-0.5
    launch_gemm_s(s0, qh, kft2, scoresF, S_, S_, KFD_, HQH_, S_, S_,
                  (long)QH_, 0L, (long)S_ * S_, scale, H_, 0, 1);
    softmax_kernel<<<dim3(S_, H_), 256, 0, s0>>>(scoresF, Ph);
    launch_gemm_s(s0, Ph, v2, attnoh, S_, VD_, S_, S_, VD_, HID_,
                  (long)S_ * S_, 0L, (long)VD_, 1.f, H_, 1, 2);

    // ---- join big weights; o-proj + MLP ----
    cudaStreamWaitEvent(s0, evWbig, 0);
    launch_gemm_s(s0, attnoh, Wo, attnprojF, S_, HID_, HID_, HID_, HID_, HID_, 0, 0, 0, 1.f, 1, 0, 0);
    rms_kernel<<<S_, 256, 0, s0>>>(attnprojF, hidden, w_post_attn, xF, HID_, 0);
    rms_kernel<<<S_, 256, 0, s0>>>(xF, nullptr, w_pre_ff, h2h, HID_, 1);
    launch_gemm_s(s0, h2h, Wgu, guh, S_, 2 * INTER_, HID_, HID_, 2 * INTER_, 2 * INTER_, 0, 0, 0, 1.f, 1, 1, 0);
    silu_mul_kernel<<<(S_ * INTER_) / 256, 256, 0, s0>>>(guh, acth);
    launch_gemm_s(s0, acth, Wdn, mlpF, S_, HID_, INTER_, INTER_, HID_, HID_, 0, 0, 0, 1.f, 1, 0, 0);
    rms_kernel<<<S_, 256, 0, s0>>>(mlpF, xF, w_post_ff, out, HID_, 0);
}